// round 6
// baseline (speedup 1.0000x reference)
#include <cuda_runtime.h>
#include <cuda_bf16.h>
#include <math.h>

// B=4, H=W=704, M=32, P=128, NN=129, R=1, GAIN=2.0
// Only batch b=3 contributes (reference returns losses[-1]).
//
// 12 CTAs x 32 threads (one warp each) to spread scattered-gather L1tex
// wavefronts across 12 SMs:
//   CTA 0..3 : pos items 32*cta + lane          (4 gathers/lane)
//   CTA 4..7 : neg items 32*(cta-4) + lane      (4 gathers/lane; item 128
//              folded into CTA 7 lane 0)
//   CTA 8..11: reg items 8*(cta-8) .. +8; lanes 0..15 = (item, anchor)
//              pairs, 14 gathers/lane; lanes 16..31 idle.
// Each CTA warp-reduces to a partial; last CTA (atomic counter) sums the 12
// partials in fixed order -> deterministic -> writes out[0], resets counter.

#define HH 704
#define WW 704
#define HWSZ (HH * WW)
#define BM 32
#define PP 128
#define NNEG 129
#define GAIN_F 2.0f
#define NCTA 12

__device__ float g_partials[NCTA];
__device__ int   g_count;   // zero-initialized at load; reset by last CTA each call

__device__ __forceinline__ float lse2(float a, float b) {
    float m = fmaxf(a, b);
    return m + __logf(__expf(a - m) + __expf(b - m));
}

__device__ __forceinline__ float smooth_l1(float d) {
    float a = fabsf(d);
    return (a < 1.0f) ? 0.5f * d * d : a - 0.5f;
}

__device__ __forceinline__ float cls_item(const float* __restrict__ pc, int2 idx,
                                          bool positive, float scale) {
    int off = idx.x * WW + idx.y;
    float l0 = pc[0 * HWSZ + off];
    float l1 = pc[1 * HWSZ + off];
    float l2 = pc[2 * HWSZ + off];
    float l3 = pc[3 * HWSZ + off];
    float v = positive ? ((lse2(l0, l1) - l1) + (lse2(l2, l3) - l3))
                       : ((lse2(l0, l1) - l0) + (lse2(l2, l3) - l2));
    return v * scale;
}

__global__ void __launch_bounds__(32, 1) loss_total_kernel(
    const float* __restrict__ ref_boxes,     // (B,M,7)
    const float* __restrict__ pred_class,    // (B,4,H,W)
    const float* __restrict__ pred_regress,  // (B,14,H,W)
    const float* __restrict__ anchor,        // (2,7,H,W)
    const int*   __restrict__ pos_idx,       // (B,P,2)
    const int*   __restrict__ neg_idx,       // (B,NN,2)
    const int*   __restrict__ reg_idx,       // (B,M,1,2)
    float* __restrict__ out)
{
    const int cta = blockIdx.x;
    const int t   = threadIdx.x;

    // batch b=3 base offsets
    const float* pc = pred_class   + (size_t)3 * 4  * HWSZ;
    const float* pr = pred_regress + (size_t)3 * 14 * HWSZ;
    const float* rb = ref_boxes    + 3 * BM * 7;
    const int2*  pi = (const int2*)(pos_idx + 3 * PP * 2);
    const int2*  ni = (const int2*)(neg_idx + 3 * NNEG * 2);
    const int2*  ri = (const int2*)(reg_idx + 3 * BM * 2);

    float local = 0.0f;

    if (cta < 4) {
        // ---- positives (label 1) ----
        int2 idx = pi[cta * 32 + t];
        local = cls_item(pc, idx, true, 1.0f / (float)PP);
    } else if (cta < 8) {
        // ---- negatives (label 0) ----
        int2 idx = ni[(cta - 4) * 32 + t];
        int2 iex = ni[(cta == 7 && t == 0) ? 128 : 0];
        local = cls_item(pc, idx, false, 1.0f / (float)NNEG);
        if (cta == 7 && t == 0)
            local += cls_item(pc, iex, false, 1.0f / (float)NNEG);
    } else {
        // ---- regression: 8 items per CTA, lanes 0..15 = (item, anchor) ----
        if (t < 16) {
            int m = (cta - 8) * 8 + (t >> 1);
            int a = t & 1;
            int2 idx = ri[m];
            int off = idx.x * WW + idx.y;

            float rv[7];
            #pragma unroll
            for (int c = 0; c < 7; c++) rv[c] = rb[m * 7 + c];

            float av[7], pv[7];
            #pragma unroll
            for (int c = 0; c < 7; c++)
                av[c] = anchor[((size_t)(a * 7 + c)) * HWSZ + off];
            #pragma unroll
            for (int c = 0; c < 7; c++)
                pv[c] = pr[((size_t)(a * 7 + c)) * HWSZ + off];

            float inv_diag = rsqrtf(av[3] * av[3] + av[4] * av[4]);
            float o0 = (rv[0] - av[0]) * inv_diag;
            float o1 = (rv[1] - av[1]) * inv_diag;
            float o2 = (rv[2] - av[2]) / av[5];
            float o3 = __logf(rv[3] / av[3]);
            float o4 = __logf(rv[4] / av[4]);
            float o5 = __logf(rv[5] / av[5]);
            // arctan2(sin(dth), cos(dth)) == wrap dth into (-pi, pi]
            float dth = rv[6] - av[6];
            float o6 = dth - 6.28318530717958647692f *
                             rintf(dth * 0.15915494309189533577f);

            float s = smooth_l1(pv[0] - o0) + smooth_l1(pv[1] - o1)
                    + smooth_l1(pv[2] - o2) + smooth_l1(pv[3] - o3)
                    + smooth_l1(pv[4] - o4) + smooth_l1(pv[5] - o5)
                    + smooth_l1(pv[6] - o6);
            local = GAIN_F * s * (1.0f / 14.0f);
        }
    }

    // ---- warp reduction ----
    #pragma unroll
    for (int s = 16; s > 0; s >>= 1)
        local += __shfl_xor_sync(0xFFFFFFFFu, local, s);

    // ---- cross-CTA reduction via device scratch + counter ----
    if (t == 0) {
        g_partials[cta] = local;
        __threadfence();
        int old = atomicAdd(&g_count, 1);
        if (old == NCTA - 1) {
            __threadfence();
            float s = 0.0f;
            #pragma unroll
            for (int i = 0; i < NCTA; i++) s += g_partials[i];
            out[0] = s;
            g_count = 0;   // reset for next graph replay
        }
    }
}

extern "C" void kernel_launch(void* const* d_in, const int* in_sizes, int n_in,
                              void* d_out, int out_size) {
    const float* ref_boxes    = (const float*)d_in[0];
    const float* pred_class   = (const float*)d_in[1];
    const float* pred_regress = (const float*)d_in[2];
    const float* anchor       = (const float*)d_in[3];
    const int*   pos_idx      = (const int*)d_in[4];
    const int*   neg_idx      = (const int*)d_in[5];
    const int*   reg_idx      = (const int*)d_in[6];
    float* out = (float*)d_out;

    loss_total_kernel<<<NCTA, 32>>>(ref_boxes, pred_class, pred_regress, anchor,
                                    pos_idx, neg_idx, reg_idx, out);
}

// round 8
// speedup vs baseline: 1.3478x; 1.3478x over previous
#include <cuda_runtime.h>
#include <cuda_bf16.h>
#include <math.h>

// B=4, H=W=704, M=32, P=128, NN=129, R=1, GAIN=2.0
// Only batch b=3 contributes (reference returns losses[-1]).
//
// Single CTA, 128 threads = 4 warps (one per SMSP: spreads MUFU + issue).
// Thread t:
//   pos item t            (4 gathers)
//   neg item t            (4 gathers; t==127 also folds neg item 128)
//   if t < 64: reg task (m = t>>1, anchor a = t&1): 7 anchor + 7 regress gathers
// All idx loads issue first (hop 1), then all gathers (hop 2), then compute.
// Cls CE uses softplus identity: lse(a,b)-b = max(a-b,0)+log1p(exp(-|a-b|))
// (2 MUFU per pair instead of 3).

#define HH 704
#define WW 704
#define HWSZ (HH * WW)
#define BM 32
#define PP 128
#define NNEG 129
#define GAIN_F 2.0f
#define NTHR 128

__device__ __forceinline__ float softplus(float d) {
    // log(1 + exp(d)) computed stably: max(d,0) + log(1 + exp(-|d|))
    return fmaxf(d, 0.0f) + __logf(1.0f + __expf(-fabsf(d)));
}

__device__ __forceinline__ float smooth_l1(float d) {
    float a = fabsf(d);
    return (a < 1.0f) ? 0.5f * d * d : a - 0.5f;
}

__global__ void __launch_bounds__(NTHR, 1) loss_total_kernel(
    const float* __restrict__ ref_boxes,     // (B,M,7)
    const float* __restrict__ pred_class,    // (B,4,H,W)
    const float* __restrict__ pred_regress,  // (B,14,H,W)
    const float* __restrict__ anchor,        // (2,7,H,W)
    const int*   __restrict__ pos_idx,       // (B,P,2)
    const int*   __restrict__ neg_idx,       // (B,NN,2)
    const int*   __restrict__ reg_idx,       // (B,M,1,2)
    float* __restrict__ out)
{
    const int t = threadIdx.x;

    // batch b=3 base offsets
    const float* pc = pred_class   + (size_t)3 * 4  * HWSZ;
    const float* pr = pred_regress + (size_t)3 * 14 * HWSZ;
    const float* rb = ref_boxes    + 3 * BM * 7;
    const int2*  pi = (const int2*)(pos_idx + 3 * PP * 2);
    const int2*  ni = (const int2*)(neg_idx + 3 * NNEG * 2);
    const int2*  ri = (const int2*)(reg_idx + 3 * BM * 2);

    // ---- hop 1: all index loads (independent) ----
    int2 ip = pi[t];
    int2 in2 = ni[t];
    int2 ix = ni[(t == 127) ? 128 : 0];   // broadcast addr for t!=127, 1 wavefront
    const int  m = t >> 1;
    const int  a = t & 1;
    int2 ir = ri[(t < 64) ? m : 0];

    // ref box (small sequential array, independent of idx chain)
    float rv[7];
    #pragma unroll
    for (int c = 0; c < 7; c++) rv[c] = rb[((t < 64) ? m : 0) * 7 + c];

    // ---- hop 2: all gathers ----
    int offp = ip.x * WW + ip.y;
    int offn = in2.x * WW + in2.y;
    int offx = ix.x * WW + ix.y;
    int offr = ir.x * WW + ir.y;

    float P0 = pc[0 * HWSZ + offp], P1 = pc[1 * HWSZ + offp];
    float P2 = pc[2 * HWSZ + offp], P3 = pc[3 * HWSZ + offp];
    float N0 = pc[0 * HWSZ + offn], N1 = pc[1 * HWSZ + offn];
    float N2 = pc[2 * HWSZ + offn], N3 = pc[3 * HWSZ + offn];
    float X0 = pc[0 * HWSZ + offx], X1 = pc[1 * HWSZ + offx];
    float X2 = pc[2 * HWSZ + offx], X3 = pc[3 * HWSZ + offx];

    float av[7], pv[7];
    #pragma unroll
    for (int c = 0; c < 7; c++)
        av[c] = anchor[((size_t)(a * 7 + c)) * HWSZ + offr];
    #pragma unroll
    for (int c = 0; c < 7; c++)
        pv[c] = pr[((size_t)(a * 7 + c)) * HWSZ + offr];

    // ---- compute ----
    // positives (label 1): lse(l0,l1)-l1 = softplus(l0-l1)
    float local = (softplus(P0 - P1) + softplus(P2 - P3)) * (1.0f / (float)PP);
    // negatives (label 0): lse(l0,l1)-l0 = softplus(l1-l0)
    local += (softplus(N1 - N0) + softplus(N3 - N2)) * (1.0f / (float)NNEG);
    if (t == 127)
        local += (softplus(X1 - X0) + softplus(X3 - X2)) * (1.0f / (float)NNEG);

    if (t < 64) {
        float inv_diag = rsqrtf(av[3] * av[3] + av[4] * av[4]);
        float o0 = (rv[0] - av[0]) * inv_diag;
        float o1 = (rv[1] - av[1]) * inv_diag;
        float o2 = (rv[2] - av[2]) / av[5];
        float o3 = __logf(rv[3] / av[3]);
        float o4 = __logf(rv[4] / av[4]);
        float o5 = __logf(rv[5] / av[5]);
        // arctan2(sin(dth), cos(dth)) == wrap dth into (-pi, pi]
        float dth = rv[6] - av[6];
        float o6 = dth - 6.28318530717958647692f *
                         rintf(dth * 0.15915494309189533577f);

        float s = smooth_l1(pv[0] - o0) + smooth_l1(pv[1] - o1)
                + smooth_l1(pv[2] - o2) + smooth_l1(pv[3] - o3)
                + smooth_l1(pv[4] - o4) + smooth_l1(pv[5] - o5)
                + smooth_l1(pv[6] - o6);
        local += GAIN_F * s * (1.0f / 14.0f);
    }

    // ---- reduction: intra-warp shuffle, 4-slot smem, warp 0 finishes ----
    #pragma unroll
    for (int s = 16; s > 0; s >>= 1)
        local += __shfl_xor_sync(0xFFFFFFFFu, local, s);

    __shared__ float wsum[4];
    const int wid = t >> 5;
    const int lid = t & 31;
    if (lid == 0) wsum[wid] = local;
    __syncthreads();

    if (wid == 0) {
        float v = (lid < 4) ? wsum[lid] : 0.0f;
        v += __shfl_xor_sync(0xFFFFFFFFu, v, 1);
        v += __shfl_xor_sync(0xFFFFFFFFu, v, 2);
        if (lid == 0) out[0] = v;
    }
}

extern "C" void kernel_launch(void* const* d_in, const int* in_sizes, int n_in,
                              void* d_out, int out_size) {
    const float* ref_boxes    = (const float*)d_in[0];
    const float* pred_class   = (const float*)d_in[1];
    const float* pred_regress = (const float*)d_in[2];
    const float* anchor       = (const float*)d_in[3];
    const int*   pos_idx      = (const int*)d_in[4];
    const int*   neg_idx      = (const int*)d_in[5];
    const int*   reg_idx      = (const int*)d_in[6];
    float* out = (float*)d_out;

    loss_total_kernel<<<1, NTHR>>>(ref_boxes, pred_class, pred_regress, anchor,
                                   pos_idx, neg_idx, reg_idx, out);
}